// round 10
// baseline (speedup 1.0000x reference)
#include <cuda_runtime.h>
#include <cuda_bf16.h>
#include <math.h>

// SpatialGRU wavefront R10: single persistent sweep kernel, software grid
// barrier between phases, M=128 full-batch items, 3-stage cp.async + ldmatrix,
// bf16x3 split-precision mma.sync GEMMs. Mutable cross-SM state read via .cg.
// B=128, C=32, L=R=80, U=128, D=416, gates NG=1024 ordered [r(384)|p(128)|z(512)].

namespace {
constexpr int B = 128, C = 32, L = 80, R = 80, U = 128;
constexpr int D = 416;
constexpr int NG = 1024;
constexpr int BP = 40;                  // smem row pitch (bf16): conflict-free ldmatrix
constexpr int ST_A = 128 * BP;          // 5120 el per sub-buffer (hi or lo)
constexpr int ST_EL = 4 * ST_A;         // [Ahi|Alo|Whi|Wlo] per stage = 20480 el
constexpr int NSTAGE = 3;
constexpr int SMEM = NSTAGE * ST_EL * 2;  // 122880 bytes
constexpr int GRID = 148;               // one CTA per SM -> all co-resident
}

__device__ __align__(128) __nv_bfloat16 g_Whi[NG * D], g_Wlo[NG * D];
__device__ __align__(128) __nv_bfloat16 g_WUhi[U * 384], g_WUlo[U * 384];
__device__ float g_bias[NG];
__device__ __align__(128) __nv_bfloat16 g_shi[L * R * B * C], g_slo[L * R * B * C];
__device__ __align__(128) __nv_bfloat16 g_Ahi[3 * L * B * D], g_Alo[3 * L * B * D];
__device__ __align__(128) __nv_bfloat16 g_rthi[L * B * 384], g_rtlo[L * B * 384];
__device__ float g_zbuf[(size_t)L * 4 * B * U];
__device__ float g_pbuf[(size_t)L * B * U];
__device__ float g_H[3][L][B * U];
__device__ unsigned g_bar;

// ---------------------------------------------------------------------------
__device__ __forceinline__ void cpa(void* dst, const void* src) {
    unsigned s = (unsigned)__cvta_generic_to_shared(dst);
    asm volatile("cp.async.cg.shared.global [%0], [%1], 16;" :: "r"(s), "l"(src));
}
__device__ __forceinline__ void cp_commit() { asm volatile("cp.async.commit_group;"); }
template <int N> __device__ __forceinline__ void cp_wait() {
    asm volatile("cp.async.wait_group %0;" :: "n"(N));
}
__device__ __forceinline__ void mma16816(float* c, const unsigned* a, const unsigned* b) {
    asm volatile(
        "mma.sync.aligned.m16n8k16.row.col.f32.bf16.bf16.f32 "
        "{%0,%1,%2,%3}, {%4,%5,%6,%7}, {%8,%9}, {%0,%1,%2,%3};"
        : "+f"(c[0]), "+f"(c[1]), "+f"(c[2]), "+f"(c[3])
        : "r"(a[0]), "r"(a[1]), "r"(a[2]), "r"(a[3]), "r"(b[0]), "r"(b[1]));
}
__device__ __forceinline__ void ldsm4(unsigned* r, const __nv_bfloat16* p) {
    unsigned a = (unsigned)__cvta_generic_to_shared(p);
    asm volatile("ldmatrix.sync.aligned.m8n8.x4.shared.b16 {%0,%1,%2,%3}, [%4];"
                 : "=r"(r[0]), "=r"(r[1]), "=r"(r[2]), "=r"(r[3]) : "r"(a));
}
__device__ __forceinline__ void ldsm2(unsigned* r, const __nv_bfloat16* p) {
    unsigned a = (unsigned)__cvta_generic_to_shared(p);
    asm volatile("ldmatrix.sync.aligned.m8n8.x2.shared.b16 {%0,%1}, [%2];"
                 : "=r"(r[0]), "=r"(r[1]) : "r"(a));
}
__device__ __forceinline__ void split2(float v, __nv_bfloat16* hi, __nv_bfloat16* lo) {
    __nv_bfloat16 h = __float2bfloat16(v);
    *hi = h;
    *lo = __float2bfloat16(v - __bfloat162float(h));
}
// L2-coherent loads for mutable cross-SM state (L1 persists within a launch).
__device__ __forceinline__ float ldcg_bf(const __nv_bfloat16* p) {
    unsigned short v;
    asm volatile("ld.global.cg.u16 %0, [%1];" : "=h"(v) : "l"(p));
    __nv_bfloat16_raw r; r.x = v;
    return __bfloat162float(__nv_bfloat16(r));
}
__device__ __forceinline__ float ldcg_f(const float* p) {
    float v;
    asm volatile("ld.global.cg.f32 %0, [%1];" : "=f"(v) : "l"(p));
    return v;
}
__device__ __forceinline__ void grid_barrier(unsigned epoch, unsigned G) {
    __syncthreads();
    if (threadIdx.x == 0) {
        __threadfence();                      // release all prior writes
        atomicAdd(&g_bar, 1u);
        const unsigned target = epoch * G;
        unsigned v;
        for (;;) {
            asm volatile("ld.acquire.gpu.global.u32 %0, [%1];" : "=r"(v) : "l"(&g_bar));
            if (v >= target) break;
            __nanosleep(64);
        }
    }
    __syncthreads();
}

// ---------------------------------------------------------------------------
__global__ void prep_kernel(const float* __restrict__ Wr, const float* __restrict__ br,
                            const float* __restrict__ Wz, const float* __restrict__ bz,
                            const float* __restrict__ Wij, const float* __restrict__ bij,
                            const float* __restrict__ WU) {
    int idx0 = blockIdx.x * blockDim.x + threadIdx.x;
    int stride = gridDim.x * blockDim.x;
    for (int i = idx0; i < NG * D; i += stride) {
        int j = i / D, k = i - j * D;
        float v;
        if (j < 384)      v = Wr[j * D + k];
        else if (j < 512) v = (k >= 384) ? Wij[(j - 384) * C + (k - 384)] : 0.0f;
        else              v = Wz[(j - 512) * D + k];
        split2(v, &g_Whi[i], &g_Wlo[i]);
    }
    for (int i = idx0; i < U * 384; i += stride)
        split2(WU[i], &g_WUhi[i], &g_WUlo[i]);
    for (int i = idx0; i < NG; i += stride)
        g_bias[i] = (i < 384) ? br[i] : (i < 512 ? bij[i - 384] : bz[i - 512]);
}

__global__ void transpose_kernel(const float* __restrict__ in) {
    __shared__ float tile[C][R + 1];
    int b = blockIdx.x, l = blockIdx.y;
    for (int i = threadIdx.x; i < C * R; i += blockDim.x) {
        int c = i / R, r = i - c * R;
        tile[c][r] = in[((b * C + c) * L + l) * R + r];
    }
    __syncthreads();
    for (int i = threadIdx.x; i < R * C; i += blockDim.x) {
        int r = i >> 5, c = i & 31;
        size_t o = (((size_t)l * R + r) * B + b) * C + c;
        split2(tile[c][r], &g_shi[o], &g_slo[o]);
    }
}

__global__ void zeroA_kernel() {
    if (blockIdx.x == 0 && threadIdx.x == 0) g_bar = 0;
    size_t n16 = (size_t)3 * L * B * D / 8;
    uint4 z = make_uint4(0, 0, 0, 0);
    for (size_t i = blockIdx.x * blockDim.x + threadIdx.x; i < n16;
         i += (size_t)gridDim.x * blockDim.x) {
        ((uint4*)g_Ahi)[i] = z;
        ((uint4*)g_Alo)[i] = z;
    }
}

// ---------------------------------------------------------------------------
__global__ void __launch_bounds__(256, 1)
sweep_kernel() {
    extern __shared__ __nv_bfloat16 sm[];
    const int tid = threadIdx.x, warp = tid >> 5, lane = tid & 31;
    const int g = lane >> 2, tig = lane & 3;
    const int lb = lane & 15;
    const unsigned G = gridDim.x;
    unsigned epoch = 0;

    for (int d = 0; d < L + R - 1; ++d) {
        int lmin = d - (R - 1); if (lmin < 0) lmin = 0;
        int lmax = (d < L - 1) ? d : (L - 1);
        int n = lmax - lmin + 1;

        // ================= phase 1: gates (item = cell*8 + ch) =================
        for (int item = blockIdx.x; item < n * 8; item += G) {
            const int cell = item >> 3, ch = item & 7;
            const int l = lmin + cell, r = d - l;
            const long abase = (((long)(d % 3) * L + l) * B) * D;
            const long sbase = (((long)l * R + r) * B) * C;
            const long wbase = (long)(ch * 128) * D;

            auto stage = [&](int kb) {
                __nv_bfloat16* st = sm + (kb % NSTAGE) * ST_EL;
                #pragma unroll
                for (int rep = 0; rep < 2; ++rep) {
                    int idx = tid + rep * 256, row = idx >> 2, q = idx & 3;
                    const __nv_bfloat16 *ah, *al;
                    if (kb < 12) {
                        long o = abase + (long)row * D + kb * 32 + q * 8;
                        ah = g_Ahi + o; al = g_Alo + o;
                    } else {
                        long o = sbase + (long)row * C + q * 8;
                        ah = g_shi + o; al = g_slo + o;
                    }
                    cpa(st + row * BP + q * 8, ah);
                    cpa(st + ST_A + row * BP + q * 8, al);
                    long wo = wbase + (long)row * D + kb * 32 + q * 8;
                    cpa(st + 2 * ST_A + row * BP + q * 8, g_Whi + wo);
                    cpa(st + 3 * ST_A + row * BP + q * 8, g_Wlo + wo);
                }
            };

            float acc[8][2][4];
            #pragma unroll
            for (int mi = 0; mi < 8; ++mi)
                #pragma unroll
                for (int ni = 0; ni < 2; ++ni)
                    #pragma unroll
                    for (int e = 0; e < 4; ++e) acc[mi][ni][e] = 0.0f;

            stage(0); cp_commit();
            stage(1); cp_commit();
            for (int kb = 0; kb < 13; ++kb) {
                if (kb + 2 < 13) { stage(kb + 2); cp_commit(); cp_wait<2>(); }
                else if (kb + 1 < 13) cp_wait<1>();
                else cp_wait<0>();
                __syncthreads();
                const __nv_bfloat16* st  = sm + (kb % NSTAGE) * ST_EL;
                const __nv_bfloat16* sAh = st;
                const __nv_bfloat16* sWh = st + 2 * ST_A;
                #pragma unroll
                for (int kk = 0; kk < 2; ++kk) {
                    int ko = kk * 16;
                    unsigned bhi[2][2], blo[2][2];
                    #pragma unroll
                    for (int ni = 0; ni < 2; ++ni) {
                        const __nv_bfloat16* pb =
                            sWh + (warp * 16 + ni * 8 + (lb & 7)) * BP + ko + ((lb >> 3) << 3);
                        ldsm2(bhi[ni], pb);
                        ldsm2(blo[ni], pb + ST_A);
                    }
                    #pragma unroll
                    for (int mig = 0; mig < 2; ++mig) {
                        unsigned ah[4][4], al[4][4];
                        #pragma unroll
                        for (int m4 = 0; m4 < 4; ++m4) {
                            const __nv_bfloat16* pa =
                                sAh + (mig * 64 + m4 * 16 + lb) * BP + ko + ((lane >> 4) << 3);
                            ldsm4(ah[m4], pa);
                            ldsm4(al[m4], pa + ST_A);
                        }
                        #pragma unroll
                        for (int m4 = 0; m4 < 4; ++m4)
                            #pragma unroll
                            for (int ni = 0; ni < 2; ++ni) {
                                float* cc = acc[mig * 4 + m4][ni];
                                mma16816(cc, ah[m4], bhi[ni]);
                                mma16816(cc, ah[m4], blo[ni]);
                                mma16816(cc, al[m4], bhi[ni]);
                            }
                    }
                }
                __syncthreads();
            }

            // ---- epilogue (uniform per ch) ----
            const int jb = ch * 128;
            if (ch < 3) {
                #pragma unroll
                for (int mi = 0; mi < 8; ++mi)
                    #pragma unroll
                    for (int ni = 0; ni < 2; ++ni)
                        #pragma unroll
                        for (int e = 0; e < 4; ++e) {
                            int bl = 16 * mi + g + 8 * (e >> 1);
                            int j = jb + warp * 16 + ni * 8 + 2 * tig + (e & 1);
                            float v = acc[mi][ni][e] + g_bias[j];
                            float rg = 1.0f / (1.0f + __expf(-v));
                            int pc = (j < 128) ? 128 + j : (j < 256 ? j - 128 : j);
                            long ai = abase + (long)bl * D + pc;
                            float hv = ldcg_bf(g_Ahi + ai) + ldcg_bf(g_Alo + ai);
                            long ri = ((long)l * B + bl) * 384 + j;
                            split2(rg * hv, &g_rthi[ri], &g_rtlo[ri]);
                        }
            } else if (ch == 3) {
                #pragma unroll
                for (int mi = 0; mi < 8; ++mi)
                    #pragma unroll
                    for (int ni = 0; ni < 2; ++ni)
                        #pragma unroll
                        for (int e = 0; e < 4; ++e) {
                            int bl = 16 * mi + g + 8 * (e >> 1);
                            int j = jb + warp * 16 + ni * 8 + 2 * tig + (e & 1);
                            g_pbuf[((size_t)l * B + bl) * U + (j - 384)] =
                                acc[mi][ni][e] + g_bias[j];
                        }
            } else {
                #pragma unroll
                for (int mi = 0; mi < 8; ++mi)
                    #pragma unroll
                    for (int ni = 0; ni < 2; ++ni)
                        #pragma unroll
                        for (int e = 0; e < 4; ++e) {
                            int bl = 16 * mi + g + 8 * (e >> 1);
                            int j = jb + warp * 16 + ni * 8 + 2 * tig + (e & 1);
                            int jz = j - 512, grp = jz >> 7, u = jz & 127;
                            g_zbuf[(((size_t)l * 4 + grp) * B + bl) * U + u] =
                                acc[mi][ni][e] + g_bias[j];
                        }
            }
        }
        grid_barrier(++epoch, G);

        // ================= phase 2: combine (item = cell) =================
        for (int item = blockIdx.x; item < n; item += G) {
            const int l = lmin + item, r = d - l;
            const long rtbase = (long)l * B * 384;

            auto stage2 = [&](int kb) {
                __nv_bfloat16* st = sm + (kb % NSTAGE) * ST_EL;
                #pragma unroll
                for (int rep = 0; rep < 2; ++rep) {
                    int idx = tid + rep * 256, row = idx >> 2, q = idx & 3;
                    long o = rtbase + (long)row * 384 + kb * 32 + q * 8;
                    cpa(st + row * BP + q * 8, g_rthi + o);
                    cpa(st + ST_A + row * BP + q * 8, g_rtlo + o);
                    long wo = (long)row * 384 + kb * 32 + q * 8;
                    cpa(st + 2 * ST_A + row * BP + q * 8, g_WUhi + wo);
                    cpa(st + 3 * ST_A + row * BP + q * 8, g_WUlo + wo);
                }
            };

            float acc[8][2][4];
            #pragma unroll
            for (int mi = 0; mi < 8; ++mi)
                #pragma unroll
                for (int ni = 0; ni < 2; ++ni)
                    #pragma unroll
                    for (int e = 0; e < 4; ++e) acc[mi][ni][e] = 0.0f;

            stage2(0); cp_commit();
            stage2(1); cp_commit();
            for (int kb = 0; kb < 12; ++kb) {
                if (kb + 2 < 12) { stage2(kb + 2); cp_commit(); cp_wait<2>(); }
                else if (kb + 1 < 12) cp_wait<1>();
                else cp_wait<0>();
                __syncthreads();
                const __nv_bfloat16* st  = sm + (kb % NSTAGE) * ST_EL;
                const __nv_bfloat16* sAh = st;
                const __nv_bfloat16* sWh = st + 2 * ST_A;
                #pragma unroll
                for (int kk = 0; kk < 2; ++kk) {
                    int ko = kk * 16;
                    unsigned bhi[2][2], blo[2][2];
                    #pragma unroll
                    for (int ni = 0; ni < 2; ++ni) {
                        const __nv_bfloat16* pb =
                            sWh + (warp * 16 + ni * 8 + (lb & 7)) * BP + ko + ((lb >> 3) << 3);
                        ldsm2(bhi[ni], pb);
                        ldsm2(blo[ni], pb + ST_A);
                    }
                    #pragma unroll
                    for (int mig = 0; mig < 2; ++mig) {
                        unsigned ah[4][4], al[4][4];
                        #pragma unroll
                        for (int m4 = 0; m4 < 4; ++m4) {
                            const __nv_bfloat16* pa =
                                sAh + (mig * 64 + m4 * 16 + lb) * BP + ko + ((lane >> 4) << 3);
                            ldsm4(ah[m4], pa);
                            ldsm4(al[m4], pa + ST_A);
                        }
                        #pragma unroll
                        for (int m4 = 0; m4 < 4; ++m4)
                            #pragma unroll
                            for (int ni = 0; ni < 2; ++ni) {
                                float* cc = acc[mig * 4 + m4][ni];
                                mma16816(cc, ah[m4], bhi[ni]);
                                mma16816(cc, ah[m4], blo[ni]);
                                mma16816(cc, al[m4], bhi[ni]);
                            }
                    }
                }
                __syncthreads();
            }

            // ---- combine + write h + scatter split(h) into future A slots ----
            const float* hT = (l > 0)          ? g_H[(d + 2) % 3][l - 1] : (const float*)0;
            const float* hL = (r > 0)          ? g_H[(d + 2) % 3][l]     : (const float*)0;
            const float* hD = (l > 0 && r > 0) ? g_H[(d + 1) % 3][l - 1] : (const float*)0;
            float* Hout = g_H[d % 3][l];
            const int nb = (d + 1) % 3, db = (d + 2) % 3;

            #pragma unroll
            for (int mi = 0; mi < 8; ++mi)
                #pragma unroll
                for (int ni = 0; ni < 2; ++ni)
                    #pragma unroll
                    for (int e = 0; e < 4; ++e) {
                        int b = 16 * mi + g + 8 * (e >> 1);
                        int u = warp * 16 + ni * 8 + 2 * tig + (e & 1);
                        float hhat = tanhf(ldcg_f(&g_pbuf[((size_t)l * B + b) * U + u]) +
                                           acc[mi][ni][e]);
                        float zi = ldcg_f(&g_zbuf[(((size_t)l * 4 + 0) * B + b) * U + u]);
                        float zl = ldcg_f(&g_zbuf[(((size_t)l * 4 + 1) * B + b) * U + u]);
                        float zt = ldcg_f(&g_zbuf[(((size_t)l * 4 + 2) * B + b) * U + u]);
                        float zd = ldcg_f(&g_zbuf[(((size_t)l * 4 + 3) * B + b) * U + u]);
                        float m = fmaxf(fmaxf(zi, zl), fmaxf(zt, zd));
                        float ei = __expf(zi - m), el = __expf(zl - m);
                        float et = __expf(zt - m), ed = __expf(zd - m);
                        int gi = b * U + u;
                        float hLv = hL ? ldcg_f(hL + gi) : 0.0f;
                        float hTv = hT ? ldcg_f(hT + gi) : 0.0f;
                        float hDv = hD ? ldcg_f(hD + gi) : 0.0f;
                        float h = (ei * hhat + el * hLv + et * hTv + ed * hDv) /
                                  (ei + el + et + ed);
                        Hout[gi] = h;
                        __nv_bfloat16 hi, lo;
                        split2(h, &hi, &lo);
                        if (l + 1 < L) {
                            long t = (((long)nb * L + (l + 1)) * B + b) * D + u;       // hT
                            g_Ahi[t] = hi; g_Alo[t] = lo;
                        }
                        if (r + 1 < R) {
                            long t = (((long)nb * L + l) * B + b) * D + 128 + u;       // hL
                            g_Ahi[t] = hi; g_Alo[t] = lo;
                        }
                        if (l + 1 < L && r + 1 < R) {
                            long t = (((long)db * L + (l + 1)) * B + b) * D + 256 + u; // hD
                            g_Ahi[t] = hi; g_Alo[t] = lo;
                        }
                    }
        }
        grid_barrier(++epoch, G);
    }
}

// ---------------------------------------------------------------------------
__global__ void out_kernel(float* __restrict__ out) {
    int i = blockIdx.x * blockDim.x + threadIdx.x;
    if (i < B * U) out[i] = g_H[(L + R - 2) % 3][L - 1][i];
}

extern "C" void kernel_launch(void* const* d_in, const int* in_sizes, int n_in,
                              void* d_out, int out_size) {
    const float* inputs = (const float*)d_in[0];
    const float* Wr  = (const float*)d_in[1];
    const float* br  = (const float*)d_in[2];
    const float* Wz  = (const float*)d_in[3];
    const float* bz  = (const float*)d_in[4];
    const float* Wij = (const float*)d_in[5];
    const float* bij = (const float*)d_in[6];
    const float* WU  = (const float*)d_in[7];

    cudaFuncSetAttribute(sweep_kernel, cudaFuncAttributeMaxDynamicSharedMemorySize, SMEM);

    prep_kernel<<<128, 256>>>(Wr, br, Wz, bz, Wij, bij, WU);
    transpose_kernel<<<dim3(B, L), 256>>>(inputs);
    zeroA_kernel<<<512, 256>>>();
    sweep_kernel<<<GRID, 256, SMEM>>>();
    out_kernel<<<64, 256>>>((float*)d_out);
}

// round 11
// speedup vs baseline: 1.3883x; 1.3883x over previous
#include <cuda_runtime.h>
#include <cuda_bf16.h>
#include <math.h>

// SpatialGRU R11: persistent dataflow wavefront. No grid barriers, no kernel
// per diagonal. Items (8 gates + 1 combine per cell) consumed in diagonal-major
// global order (linear extension of dep DAG -> deadlock-free, all CTAs resident).
// Per-cell release/acquire flags. Per-cell permanent h storage (no rotation,
// no WAR hazards). bf16x3 split mma.sync GEMMs, 512 thr/CTA, 3-stage cp.async.

namespace {
constexpr int B = 128, C = 32, L = 80, R = 80, U = 128;
constexpr int D = 416, NG = 1024, BU = B * U;
constexpr int BP = 40;                 // smem row pitch (bf16), conflict-free ldmatrix
constexpr int ST_A = 128 * BP;         // 5120 el per sub-buffer
constexpr int ST_EL = 4 * ST_A;        // [Ahi|Alo|Whi|Wlo] = 20480 el per stage
constexpr int NSTAGE = 3;
constexpr int SMEM = NSTAGE * ST_EL * 2;   // 122880 B
constexpr int GRID = 148;
constexpr int NCELL = L * R;
}

__device__ __align__(128) __nv_bfloat16 g_Whi[NG * D], g_Wlo[NG * D];
__device__ __align__(128) __nv_bfloat16 g_WUhi[U * 384], g_WUlo[U * 384];
__device__ float g_bias[NG];
__device__ __align__(128) __nv_bfloat16 g_shi[NCELL * B * C], g_slo[NCELL * B * C];
__device__ __align__(128) __nv_bfloat16 g_hhi[(size_t)NCELL * BU];
__device__ __align__(128) __nv_bfloat16 g_hlo[(size_t)NCELL * BU];
__device__ float g_Hfull[(size_t)NCELL * BU];
__device__ __align__(128) __nv_bfloat16 g_rthi[(size_t)R * B * 384];
__device__ __align__(128) __nv_bfloat16 g_rtlo[(size_t)R * B * 384];
__device__ float g_z[(size_t)R * 4 * B * U];
__device__ float g_p[(size_t)R * B * U];
__device__ unsigned g_cnt[NCELL];    // gates-done counter per cell (target 8)
__device__ unsigned g_flag[NCELL];   // h published flag per cell

// ---------------------------------------------------------------------------
__device__ __forceinline__ void cpaz(void* dst, const void* src, bool valid) {
    unsigned s = (unsigned)__cvta_generic_to_shared(dst);
    int sz = valid ? 16 : 0;   // src-size 0 => zero-fill
    asm volatile("cp.async.cg.shared.global [%0], [%1], 16, %2;"
                 :: "r"(s), "l"(src), "r"(sz));
}
__device__ __forceinline__ void cp_commit() { asm volatile("cp.async.commit_group;"); }
template <int N> __device__ __forceinline__ void cp_wait() {
    asm volatile("cp.async.wait_group %0;" :: "n"(N));
}
__device__ __forceinline__ void mma16816(float* c, const unsigned* a, const unsigned* b) {
    asm volatile(
        "mma.sync.aligned.m16n8k16.row.col.f32.bf16.bf16.f32 "
        "{%0,%1,%2,%3}, {%4,%5,%6,%7}, {%8,%9}, {%0,%1,%2,%3};"
        : "+f"(c[0]), "+f"(c[1]), "+f"(c[2]), "+f"(c[3])
        : "r"(a[0]), "r"(a[1]), "r"(a[2]), "r"(a[3]), "r"(b[0]), "r"(b[1]));
}
__device__ __forceinline__ void ldsm4(unsigned* r, const __nv_bfloat16* p) {
    unsigned a = (unsigned)__cvta_generic_to_shared(p);
    asm volatile("ldmatrix.sync.aligned.m8n8.x4.shared.b16 {%0,%1,%2,%3}, [%4];"
                 : "=r"(r[0]), "=r"(r[1]), "=r"(r[2]), "=r"(r[3]) : "r"(a));
}
__device__ __forceinline__ void ldsm2(unsigned* r, const __nv_bfloat16* p) {
    unsigned a = (unsigned)__cvta_generic_to_shared(p);
    asm volatile("ldmatrix.sync.aligned.m8n8.x2.shared.b16 {%0,%1}, [%2];"
                 : "=r"(r[0]), "=r"(r[1]) : "r"(a));
}
__device__ __forceinline__ void split2(float v, __nv_bfloat16* hi, __nv_bfloat16* lo) {
    __nv_bfloat16 h = __float2bfloat16(v);
    *hi = h;
    *lo = __float2bfloat16(v - __bfloat162float(h));
}
__device__ __forceinline__ float ldcg_f(const float* p) {
    float v;
    asm volatile("ld.global.cg.f32 %0, [%1];" : "=f"(v) : "l"(p));
    return v;
}
__device__ __forceinline__ void spin_ge(const unsigned* p, unsigned target) {
    unsigned v, ns = 64;
    for (;;) {
        asm volatile("ld.acquire.gpu.global.u32 %0, [%1];" : "=r"(v) : "l"(p));
        if (v >= target) return;
        __nanosleep(ns);
        if (ns < 2048) ns <<= 1;
    }
}

// ---------------------------------------------------------------------------
__global__ void prep_kernel(const float* __restrict__ Wr, const float* __restrict__ br,
                            const float* __restrict__ Wz, const float* __restrict__ bz,
                            const float* __restrict__ Wij, const float* __restrict__ bij,
                            const float* __restrict__ WU) {
    int idx0 = blockIdx.x * blockDim.x + threadIdx.x;
    int stride = gridDim.x * blockDim.x;
    for (int i = idx0; i < NG * D; i += stride) {
        int j = i / D, k = i - j * D;
        float v;
        if (j < 384)      v = Wr[j * D + k];
        else if (j < 512) v = (k >= 384) ? Wij[(j - 384) * C + (k - 384)] : 0.0f;
        else              v = Wz[(j - 512) * D + k];
        split2(v, &g_Whi[i], &g_Wlo[i]);
    }
    for (int i = idx0; i < U * 384; i += stride)
        split2(WU[i], &g_WUhi[i], &g_WUlo[i]);
    for (int i = idx0; i < NG; i += stride)
        g_bias[i] = (i < 384) ? br[i] : (i < 512 ? bij[i - 384] : bz[i - 512]);
}

__global__ void transpose_kernel(const float* __restrict__ in) {
    __shared__ float tile[C][R + 1];
    int b = blockIdx.x, l = blockIdx.y;
    for (int i = threadIdx.x; i < C * R; i += blockDim.x) {
        int c = i / R, r = i - c * R;
        tile[c][r] = in[((b * C + c) * L + l) * R + r];
    }
    __syncthreads();
    for (int i = threadIdx.x; i < R * C; i += blockDim.x) {
        int r = i >> 5, c = i & 31;
        size_t o = (((size_t)l * R + r) * B + b) * C + c;
        split2(tile[c][r], &g_shi[o], &g_slo[o]);
    }
}

__global__ void init_kernel() {
    for (int i = blockIdx.x * blockDim.x + threadIdx.x; i < NCELL;
         i += gridDim.x * blockDim.x) {
        g_cnt[i] = 0;
        g_flag[i] = 0;
    }
}

// ---------------------------------------------------------------------------
__global__ void __launch_bounds__(512, 1)
sweep_kernel() {
    extern __shared__ __nv_bfloat16 sm[];
    const int tid = threadIdx.x, warp = tid >> 5, lane = tid & 31;
    const int warp_m = warp & 3, warp_n = warp >> 2;
    const int g = lane >> 2, tig = lane & 3, lb = lane & 15;
    const int G = (int)gridDim.x, blk = (int)blockIdx.x;
    long base = 0;

    for (int d = 0; d < L + R - 1; ++d) {
        int lmin = d - (R - 1); if (lmin < 0) lmin = 0;
        int lmax = (d < L - 1) ? d : (L - 1);
        const int n = lmax - lmin + 1;
        const int total = n * 9;
        int q0 = (blk - (int)(base % G)) % G; if (q0 < 0) q0 += G;

        for (int q = q0; q < total; q += G) {
            const bool is_gate = (q < n * 8);
            const int cell = is_gate ? (q >> 3) : (q - n * 8);
            const int ch = is_gate ? (q & 7) : 0;
            const int l = lmin + cell, r = d - l;
            const int cellG = l * R + r;
            const int cellT = (l > 0)          ? (l - 1) * R + r       : -1;
            const int cellL = (r > 0)          ? l * R + (r - 1)       : -1;
            const int cellD = (l > 0 && r > 0) ? (l - 1) * R + (r - 1) : -1;

            float acc[2][4][4];
            #pragma unroll
            for (int mi = 0; mi < 2; ++mi)
                #pragma unroll
                for (int ni = 0; ni < 4; ++ni)
                    #pragma unroll
                    for (int e = 0; e < 4; ++e) acc[mi][ni][e] = 0.0f;

            auto gemm_kb = [&](int kb) {
                const __nv_bfloat16* st = sm + (kb % NSTAGE) * ST_EL;
                const __nv_bfloat16* sA = st;
                const __nv_bfloat16* sW = st + 2 * ST_A;
                #pragma unroll
                for (int kk = 0; kk < 2; ++kk) {
                    int ko = kk * 16;
                    unsigned bhi[4][2], blo[4][2];
                    #pragma unroll
                    for (int ni = 0; ni < 4; ++ni) {
                        const __nv_bfloat16* pb =
                            sW + (warp_n * 32 + ni * 8 + (lb & 7)) * BP + ko + ((lb >> 3) << 3);
                        ldsm2(bhi[ni], pb);
                        ldsm2(blo[ni], pb + ST_A);
                    }
                    unsigned ah[2][4], al[2][4];
                    #pragma unroll
                    for (int mi = 0; mi < 2; ++mi) {
                        const __nv_bfloat16* pa =
                            sA + (warp_m * 32 + mi * 16 + lb) * BP + ko + ((lane >> 4) << 3);
                        ldsm4(ah[mi], pa);
                        ldsm4(al[mi], pa + ST_A);
                    }
                    #pragma unroll
                    for (int mi = 0; mi < 2; ++mi)
                        #pragma unroll
                        for (int ni = 0; ni < 4; ++ni) {
                            float* cc = acc[mi][ni];
                            mma16816(cc, ah[mi], bhi[ni]);
                            mma16816(cc, ah[mi], blo[ni]);
                            mma16816(cc, al[mi], bhi[ni]);
                        }
                }
            };

            if (is_gate) {
                // ---------------- gates item: M=128, N=128, K=416 ----------------
                if (tid == 0) {
                    if (cellT >= 0) spin_ge(&g_flag[cellT], 1u);
                    if (cellL >= 0) spin_ge(&g_flag[cellL], 1u);
                    if (cellD >= 0) spin_ge(&g_flag[cellD], 1u);
                }
                __syncthreads();

                auto stage = [&](int kb) {
                    __nv_bfloat16* st = sm + (kb % NSTAGE) * ST_EL;
                    #pragma unroll
                    for (int rep = 0; rep < 4; ++rep) {
                        int idx = tid + rep * 512;
                        int buf = idx >> 9, e = idx & 511, row = e >> 2, qq = e & 3;
                        if (buf < 2) {
                            const __nv_bfloat16* sp; bool valid = true;
                            if (kb < 12) {
                                int part = kb >> 2;
                                int cx = (part == 0) ? cellT : (part == 1 ? cellL : cellD);
                                valid = cx >= 0;
                                long o = (long)(valid ? cx : 0) * BU + row * 128 +
                                         (kb & 3) * 32 + qq * 8;
                                sp = (buf == 0 ? g_hhi : g_hlo) + o;
                            } else {
                                long o = ((long)cellG * B + row) * C + qq * 8;
                                sp = (buf == 0 ? g_shi : g_slo) + o;
                            }
                            cpaz(st + buf * ST_A + row * BP + qq * 8, sp, valid);
                        } else {
                            long o = (long)(ch * 128 + row) * D + kb * 32 + qq * 8;
                            cpaz(st + buf * ST_A + row * BP + qq * 8,
                                 (buf == 2 ? g_Whi : g_Wlo) + o, true);
                        }
                    }
                };

                stage(0); cp_commit();
                stage(1); cp_commit();
                for (int kb = 0; kb < 13; ++kb) {
                    if (kb + 2 < 13) { stage(kb + 2); cp_commit(); cp_wait<2>(); }
                    else if (kb + 1 < 13) cp_wait<1>();
                    else cp_wait<0>();
                    __syncthreads();
                    gemm_kb(kb);
                    __syncthreads();
                }

                // epilogue (uniform per ch)
                if (ch < 3) {
                    const float* hsrc =
                        (ch == 0) ? (cellL >= 0 ? g_Hfull + (size_t)cellL * BU : (const float*)0)
                      : (ch == 1) ? (cellT >= 0 ? g_Hfull + (size_t)cellT * BU : (const float*)0)
                                  : (cellD >= 0 ? g_Hfull + (size_t)cellD * BU : (const float*)0);
                    const size_t rtb = (size_t)r * B * 384;
                    #pragma unroll
                    for (int mi = 0; mi < 2; ++mi)
                        #pragma unroll
                        for (int ni = 0; ni < 4; ++ni)
                            #pragma unroll
                            for (int e = 0; e < 4; ++e) {
                                int row = warp_m * 32 + mi * 16 + g + 8 * (e >> 1);
                                int col = warp_n * 32 + ni * 8 + 2 * tig + (e & 1);
                                int j = ch * 128 + col;
                                float v = acc[mi][ni][e] + g_bias[j];
                                float rg = 1.0f / (1.0f + __expf(-v));
                                float hv = hsrc ? ldcg_f(hsrc + row * U + col) : 0.0f;
                                split2(rg * hv, &g_rthi[rtb + (size_t)row * 384 + j],
                                                &g_rtlo[rtb + (size_t)row * 384 + j]);
                            }
                } else if (ch == 3) {
                    #pragma unroll
                    for (int mi = 0; mi < 2; ++mi)
                        #pragma unroll
                        for (int ni = 0; ni < 4; ++ni)
                            #pragma unroll
                            for (int e = 0; e < 4; ++e) {
                                int row = warp_m * 32 + mi * 16 + g + 8 * (e >> 1);
                                int col = warp_n * 32 + ni * 8 + 2 * tig + (e & 1);
                                g_p[((size_t)r * B + row) * U + col] =
                                    acc[mi][ni][e] + g_bias[384 + col];
                            }
                } else {
                    const int grp = ch - 4;
                    #pragma unroll
                    for (int mi = 0; mi < 2; ++mi)
                        #pragma unroll
                        for (int ni = 0; ni < 4; ++ni)
                            #pragma unroll
                            for (int e = 0; e < 4; ++e) {
                                int row = warp_m * 32 + mi * 16 + g + 8 * (e >> 1);
                                int col = warp_n * 32 + ni * 8 + 2 * tig + (e & 1);
                                g_z[(((size_t)r * 4 + grp) * B + row) * U + col] =
                                    acc[mi][ni][e] + g_bias[512 + grp * 128 + col];
                            }
                }
                __syncthreads();
                if (tid == 0) {
                    __threadfence();
                    asm volatile("red.release.gpu.global.add.u32 [%0], %1;"
                                 :: "l"(&g_cnt[cellG]), "r"(1u));
                }
            } else {
                // ---------------- combine item: M=128, N=128, K=384 ----------------
                if (tid == 0) spin_ge(&g_cnt[cellG], 8u);
                __syncthreads();

                auto stage = [&](int kb) {
                    __nv_bfloat16* st = sm + (kb % NSTAGE) * ST_EL;
                    #pragma unroll
                    for (int rep = 0; rep < 4; ++rep) {
                        int idx = tid + rep * 512;
                        int buf = idx >> 9, e = idx & 511, row = e >> 2, qq = e & 3;
                        if (buf < 2) {
                            long o = ((size_t)r * B + row) * 384 + kb * 32 + qq * 8;
                            cpaz(st + buf * ST_A + row * BP + qq * 8,
                                 (buf == 0 ? g_rthi : g_rtlo) + o, true);
                        } else {
                            long o = (long)row * 384 + kb * 32 + qq * 8;
                            cpaz(st + buf * ST_A + row * BP + qq * 8,
                                 (buf == 2 ? g_WUhi : g_WUlo) + o, true);
                        }
                    }
                };

                stage(0); cp_commit();
                stage(1); cp_commit();
                for (int kb = 0; kb < 12; ++kb) {
                    if (kb + 2 < 12) { stage(kb + 2); cp_commit(); cp_wait<2>(); }
                    else if (kb + 1 < 12) cp_wait<1>();
                    else cp_wait<0>();
                    __syncthreads();
                    gemm_kb(kb);
                    __syncthreads();
                }

                const float* HL = (cellL >= 0) ? g_Hfull + (size_t)cellL * BU : (const float*)0;
                const float* HT = (cellT >= 0) ? g_Hfull + (size_t)cellT * BU : (const float*)0;
                const float* HD = (cellD >= 0) ? g_Hfull + (size_t)cellD * BU : (const float*)0;
                #pragma unroll
                for (int mi = 0; mi < 2; ++mi)
                    #pragma unroll
                    for (int ni = 0; ni < 4; ++ni)
                        #pragma unroll
                        for (int e = 0; e < 4; ++e) {
                            int b = warp_m * 32 + mi * 16 + g + 8 * (e >> 1);
                            int u = warp_n * 32 + ni * 8 + 2 * tig + (e & 1);
                            float hhat = tanhf(ldcg_f(&g_p[((size_t)r * B + b) * U + u]) +
                                               acc[mi][ni][e]);
                            float zi = ldcg_f(&g_z[(((size_t)r * 4 + 0) * B + b) * U + u]);
                            float zl = ldcg_f(&g_z[(((size_t)r * 4 + 1) * B + b) * U + u]);
                            float zt = ldcg_f(&g_z[(((size_t)r * 4 + 2) * B + b) * U + u]);
                            float zd = ldcg_f(&g_z[(((size_t)r * 4 + 3) * B + b) * U + u]);
                            float m = fmaxf(fmaxf(zi, zl), fmaxf(zt, zd));
                            float ei = __expf(zi - m), el = __expf(zl - m);
                            float et = __expf(zt - m), ed = __expf(zd - m);
                            int gi = b * U + u;
                            float hLv = HL ? ldcg_f(HL + gi) : 0.0f;
                            float hTv = HT ? ldcg_f(HT + gi) : 0.0f;
                            float hDv = HD ? ldcg_f(HD + gi) : 0.0f;
                            float h = (ei * hhat + el * hLv + et * hTv + ed * hDv) /
                                      (ei + el + et + ed);
                            size_t o = (size_t)cellG * BU + gi;
                            g_Hfull[o] = h;
                            split2(h, &g_hhi[o], &g_hlo[o]);
                        }
                __syncthreads();
                if (tid == 0) {
                    __threadfence();
                    asm volatile("st.release.gpu.global.u32 [%0], %1;"
                                 :: "l"(&g_flag[cellG]), "r"(1u));
                }
            }
        }
        base += total;
    }
}

// ---------------------------------------------------------------------------
__global__ void out_kernel(float* __restrict__ out) {
    int i = blockIdx.x * blockDim.x + threadIdx.x;
    if (i < BU) out[i] = g_Hfull[(size_t)(NCELL - 1) * BU + i];
}

extern "C" void kernel_launch(void* const* d_in, const int* in_sizes, int n_in,
                              void* d_out, int out_size) {
    const float* inputs = (const float*)d_in[0];
    const float* Wr  = (const float*)d_in[1];
    const float* br  = (const float*)d_in[2];
    const float* Wz  = (const float*)d_in[3];
    const float* bz  = (const float*)d_in[4];
    const float* Wij = (const float*)d_in[5];
    const float* bij = (const float*)d_in[6];
    const float* WU  = (const float*)d_in[7];

    cudaFuncSetAttribute(sweep_kernel, cudaFuncAttributeMaxDynamicSharedMemorySize, SMEM);

    prep_kernel<<<128, 256>>>(Wr, br, Wz, bz, Wij, bij, WU);
    transpose_kernel<<<dim3(B, L), 256>>>(inputs);
    init_kernel<<<26, 256>>>();
    sweep_kernel<<<GRID, 512, SMEM>>>();
    out_kernel<<<64, 256>>>((float*)d_out);
}